// round 2
// baseline (speedup 1.0000x reference)
#include <cuda_runtime.h>
#include <math.h>

// Problem constants (fixed by the dataset)
#define Cn   128          // channels
#define Hh   5            // heads
#define HC   (Hh*Cn)      // 640
#define MAXN 20000
#define MAXE 320000
#define MAXET (MAXE + MAXN)
#define EPSV 1e-16f
#define NEG_SLOPE 0.2f

// ---------------- scratch (static device globals; no runtime alloc) ----------
__device__ float g_h[(size_t)MAXN * HC];       // projected features [N,H,C] (51.2 MB)
__device__ float g_asrc[MAXN * Hh];
__device__ float g_adst[MAXN * Hh];
__device__ float g_emax[MAXN * Hh];
__device__ float g_denom[MAXN * Hh];
__device__ float g_exp[(size_t)MAXET * Hh];

__device__ __forceinline__ void atomicMaxFloat(float* addr, float v) {
    if (v >= 0.0f) atomicMax((int*)addr, __float_as_int(v));
    else           atomicMin((unsigned int*)addr, __float_as_uint(v));
}

// ---------------- kernel 0: init out = features + bias; reset softmax stats --
__global__ void init_kernel(const float* __restrict__ features,
                            const float* __restrict__ bias,
                            float* __restrict__ out, int Nn) {
    int i = blockIdx.x * blockDim.x + threadIdx.x;
    int NC = Nn * Cn;
    if (i < NC) out[i] = features[i] + bias[i & (Cn - 1)];
    if (i < Nn * Hh) { g_emax[i] = -3.4e38f; g_denom[i] = 0.0f; }
}

// ---------------- kernel 1: SGEMM g_h = features[N,128] @ W[128,640] ---------
#define BM 128
#define BN 128
#define BK 8
#define TM 8
#define TN 8
__global__ __launch_bounds__(256, 2)
void sgemm_kernel(const float* __restrict__ A,
                  const float* __restrict__ B,
                  int M) {
    __shared__ float As[BK][BM];
    __shared__ float Bs[BK][BN];

    const int tid    = threadIdx.x;
    const int rowBlk = blockIdx.y * BM;
    const int colBlk = blockIdx.x * BN;

    const int tx = tid & 15;
    const int ty = tid >> 4;

    const int aRow  = tid >> 1;
    const int aCol4 = (tid & 1) << 2;
    const int bRow  = tid >> 5;
    const int bCol4 = (tid & 31) << 2;

    float acc[TM][TN];
    #pragma unroll
    for (int i = 0; i < TM; i++)
        #pragma unroll
        for (int j = 0; j < TN; j++) acc[i][j] = 0.0f;

    for (int k0 = 0; k0 < Cn; k0 += BK) {
        float4 av = make_float4(0.f, 0.f, 0.f, 0.f);
        int gRow = rowBlk + aRow;
        if (gRow < M)
            av = *(const float4*)(A + (size_t)gRow * Cn + k0 + aCol4);
        As[aCol4 + 0][aRow] = av.x;
        As[aCol4 + 1][aRow] = av.y;
        As[aCol4 + 2][aRow] = av.z;
        As[aCol4 + 3][aRow] = av.w;
        float4 bv = *(const float4*)(B + (size_t)(k0 + bRow) * HC + colBlk + bCol4);
        *(float4*)&Bs[bRow][bCol4] = bv;
        __syncthreads();

        #pragma unroll
        for (int k = 0; k < BK; k++) {
            float a[TM], b[TN];
            float4 a0 = *(const float4*)&As[k][ty * TM];
            float4 a1 = *(const float4*)&As[k][ty * TM + 4];
            a[0]=a0.x; a[1]=a0.y; a[2]=a0.z; a[3]=a0.w;
            a[4]=a1.x; a[5]=a1.y; a[6]=a1.z; a[7]=a1.w;
            float4 b0 = *(const float4*)&Bs[k][tx * TN];
            float4 b1 = *(const float4*)&Bs[k][tx * TN + 4];
            b[0]=b0.x; b[1]=b0.y; b[2]=b0.z; b[3]=b0.w;
            b[4]=b1.x; b[5]=b1.y; b[6]=b1.z; b[7]=b1.w;
            #pragma unroll
            for (int i = 0; i < TM; i++)
                #pragma unroll
                for (int j = 0; j < TN; j++)
                    acc[i][j] = fmaf(a[i], b[j], acc[i][j]);
        }
        __syncthreads();
    }

    #pragma unroll
    for (int i = 0; i < TM; i++) {
        int gRow = rowBlk + ty * TM + i;
        if (gRow < M) {
            float* cp = g_h + (size_t)gRow * HC + colBlk + tx * TN;
            *(float4*)cp       = make_float4(acc[i][0], acc[i][1], acc[i][2], acc[i][3]);
            *(float4*)(cp + 4) = make_float4(acc[i][4], acc[i][5], acc[i][6], acc[i][7]);
        }
    }
}

// ---------------- kernel 2: per-(node,head) attention logits ------------------
__global__ void alpha_kernel(const float* __restrict__ att_src,
                             const float* __restrict__ att_dst,
                             int Npairs) {
    int warpId = (blockIdx.x * blockDim.x + threadIdx.x) >> 5;
    int lane   = threadIdx.x & 31;
    if (warpId >= Npairs) return;
    int n = warpId / Hh;
    int h = warpId - n * Hh;
    const float* hp = g_h + (size_t)n * HC + h * Cn;
    const float* as = att_src + h * Cn;
    const float* ad = att_dst + h * Cn;
    float s = 0.f, d = 0.f;
    #pragma unroll
    for (int c = lane; c < Cn; c += 32) {
        float v = hp[c];
        s = fmaf(v, as[c], s);
        d = fmaf(v, ad[c], d);
    }
    #pragma unroll
    for (int o = 16; o; o >>= 1) {
        s += __shfl_down_sync(0xffffffffu, s, o);
        d += __shfl_down_sync(0xffffffffu, d, o);
    }
    if (lane == 0) { g_asrc[warpId] = s; g_adst[warpId] = d; }
}

// ---------------- kernel 3: segment max ---------------------------------------
__global__ void emax_kernel(const int* __restrict__ ei, int E, int Etot) {
    int idx = blockIdx.x * blockDim.x + threadIdx.x;
    if (idx >= Etot * Hh) return;
    int e = idx / Hh;
    int h = idx - e * Hh;
    int src, dst;
    if (e < E) { src = ei[e]; dst = ei[E + e]; }
    else       { src = e - E; dst = src; }
    float v = g_asrc[src * Hh + h] + g_adst[dst * Hh + h];
    v = v > 0.f ? v : NEG_SLOPE * v;
    atomicMaxFloat(&g_emax[dst * Hh + h], v);
}

// ---------------- kernel 4: exp + segment sum ---------------------------------
__global__ void denom_kernel(const int* __restrict__ ei, int E, int Etot) {
    int idx = blockIdx.x * blockDim.x + threadIdx.x;
    if (idx >= Etot * Hh) return;
    int e = idx / Hh;
    int h = idx - e * Hh;
    int src, dst;
    if (e < E) { src = ei[e]; dst = ei[E + e]; }
    else       { src = e - E; dst = src; }
    float v = g_asrc[src * Hh + h] + g_adst[dst * Hh + h];
    v = v > 0.f ? v : NEG_SLOPE * v;
    float t = __expf(v - g_emax[dst * Hh + h]);
    g_exp[idx] = t;
    atomicAdd(&g_denom[dst * Hh + h], t);
}

// ---------------- kernel 5: weighted scatter-sum, head-mean folded in ---------
__global__ __launch_bounds__(Cn)
void scatter_kernel(const int* __restrict__ ei,
                    float* __restrict__ out, int E) {
    int e = blockIdx.x;
    int src, dst;
    if (e < E) { src = ei[e]; dst = ei[E + e]; }
    else       { src = e - E; dst = src; }

    __shared__ float w[Hh];
    int t = threadIdx.x;
    if (t < Hh) {
        float num = g_exp[(size_t)e * Hh + t];
        float den = g_denom[dst * Hh + t];
        w[t] = num / (den + EPSV) * (1.0f / Hh);
    }
    __syncthreads();

    const float* hp = g_h + (size_t)src * HC + t;
    float acc = 0.f;
    #pragma unroll
    for (int hh = 0; hh < Hh; hh++)
        acc = fmaf(w[hh], hp[hh * Cn], acc);
    atomicAdd(&out[dst * Cn + t], acc);
}

// ---------------- launch ------------------------------------------------------
extern "C" void kernel_launch(void* const* d_in, const int* in_sizes, int n_in,
                              void* d_out, int out_size) {
    const float* features = (const float*)d_in[0];
    const float* W        = (const float*)d_in[1];
    const float* att_src  = (const float*)d_in[2];
    const float* att_dst  = (const float*)d_in[3];
    const float* bias     = (const float*)d_in[4];
    const int*   ei       = (const int*)d_in[5];   // int32: jax default x64 off
    float*       out      = (float*)d_out;

    const int Nn   = in_sizes[0] / Cn;   // 20000
    const int E    = in_sizes[5] / 2;    // 320000
    const int Etot = E + Nn;             // 340000

    // 0) out = features + bias; reset softmax stats
    {
        int work = Nn * Cn;
        init_kernel<<<(work + 255) / 256, 256>>>(features, bias, out, Nn);
    }

    // 1) h = features @ W  (writes device global g_h directly)
    {
        dim3 grid(HC / BN, (Nn + BM - 1) / BM);   // (5, 157)
        sgemm_kernel<<<grid, 256>>>(features, W, Nn);
    }

    // 2) attention logits: one warp per (n,h)
    {
        int pairs  = Nn * Hh;                     // 100000
        int blocks = (pairs + 7) / 8;             // 8 warps per 256-thread block
        alpha_kernel<<<blocks, 256>>>(att_src, att_dst, pairs);
    }

    // 3) segment max
    {
        int work = Etot * Hh;
        emax_kernel<<<(work + 255) / 256, 256>>>(ei, E, Etot);
    }

    // 4) exp + segment sum
    {
        int work = Etot * Hh;
        denom_kernel<<<(work + 255) / 256, 256>>>(ei, E, Etot);
    }

    // 5) weighted scatter into out
    scatter_kernel<<<Etot, Cn>>>(ei, out, E);
}

// round 3
// speedup vs baseline: 1.6498x; 1.6498x over previous
#include <cuda_runtime.h>
#include <math.h>

// Problem constants (fixed by the dataset)
#define Cn   128          // channels
#define Hh   5            // heads
#define HC   (Hh*Cn)      // 640
#define MAXN 20000
#define MAXE 320000
#define MAXET (MAXE + MAXN)
#define EPSV 1e-16f
#define NEG_SLOPE 0.2f

// ---------------- scratch (static device globals; no runtime alloc) ----------
__device__ float g_h[(size_t)MAXN * HC];       // projected features [N,H,C] (51.2 MB)
__device__ float g_asrc[MAXN * Hh];
__device__ float g_adst[MAXN * Hh];
__device__ float g_denom[MAXN * Hh];

// ---------------- kernel 0: init out = features + bias; zero denom ----------
__global__ void init_kernel(const float* __restrict__ features,
                            const float* __restrict__ bias,
                            float* __restrict__ out, int Nn) {
    int i = blockIdx.x * blockDim.x + threadIdx.x;
    int NC = Nn * Cn;
    if (i < NC) out[i] = features[i] + bias[i & (Cn - 1)];
    if (i < Nn * Hh) g_denom[i] = 0.0f;
}

// ---------------- kernel 1: SGEMM g_h = features @ W, fused attention logits -
// Each block computes a 128x128 tile = (128 rows) x (one full head), so the
// per-(row,head) dot products with att_src/att_dst reduce entirely in-block.
#define BM 128
#define BN 128
#define BK 8
#define TM 8
#define TN 8
__global__ __launch_bounds__(256, 2)
void sgemm_kernel(const float* __restrict__ A,
                  const float* __restrict__ B,
                  const float* __restrict__ att_src,
                  const float* __restrict__ att_dst,
                  int M) {
    __shared__ float As[BK][BM];
    __shared__ float Bs[BK][BN];

    const int tid    = threadIdx.x;
    const int rowBlk = blockIdx.y * BM;
    const int head   = blockIdx.x;          // BN == Cn: one head per block col
    const int colBlk = head * BN;

    const int tx = tid & 15;
    const int ty = tid >> 4;

    const int aRow  = tid >> 1;
    const int aCol4 = (tid & 1) << 2;
    const int bRow  = tid >> 5;
    const int bCol4 = (tid & 31) << 2;

    float acc[TM][TN];
    #pragma unroll
    for (int i = 0; i < TM; i++)
        #pragma unroll
        for (int j = 0; j < TN; j++) acc[i][j] = 0.0f;

    for (int k0 = 0; k0 < Cn; k0 += BK) {
        float4 av = make_float4(0.f, 0.f, 0.f, 0.f);
        int gRow = rowBlk + aRow;
        if (gRow < M)
            av = *(const float4*)(A + (size_t)gRow * Cn + k0 + aCol4);
        As[aCol4 + 0][aRow] = av.x;
        As[aCol4 + 1][aRow] = av.y;
        As[aCol4 + 2][aRow] = av.z;
        As[aCol4 + 3][aRow] = av.w;
        float4 bv = *(const float4*)(B + (size_t)(k0 + bRow) * HC + colBlk + bCol4);
        *(float4*)&Bs[bRow][bCol4] = bv;
        __syncthreads();

        #pragma unroll
        for (int k = 0; k < BK; k++) {
            float a[TM], b[TN];
            float4 a0 = *(const float4*)&As[k][ty * TM];
            float4 a1 = *(const float4*)&As[k][ty * TM + 4];
            a[0]=a0.x; a[1]=a0.y; a[2]=a0.z; a[3]=a0.w;
            a[4]=a1.x; a[5]=a1.y; a[6]=a1.z; a[7]=a1.w;
            float4 b0 = *(const float4*)&Bs[k][tx * TN];
            float4 b1 = *(const float4*)&Bs[k][tx * TN + 4];
            b[0]=b0.x; b[1]=b0.y; b[2]=b0.z; b[3]=b0.w;
            b[4]=b1.x; b[5]=b1.y; b[6]=b1.z; b[7]=b1.w;
            #pragma unroll
            for (int i = 0; i < TM; i++)
                #pragma unroll
                for (int j = 0; j < TN; j++)
                    acc[i][j] = fmaf(a[i], b[j], acc[i][j]);
        }
        __syncthreads();
    }

    // store h tile
    #pragma unroll
    for (int i = 0; i < TM; i++) {
        int gRow = rowBlk + ty * TM + i;
        if (gRow < M) {
            float* cp = g_h + (size_t)gRow * HC + colBlk + tx * TN;
            *(float4*)cp       = make_float4(acc[i][0], acc[i][1], acc[i][2], acc[i][3]);
            *(float4*)(cp + 4) = make_float4(acc[i][4], acc[i][5], acc[i][6], acc[i][7]);
        }
    }

    // fused attention logits: per-row dot with att_src/att_dst for this head.
    // thread partial over its 8 columns, then reduce across tx (16 lanes =
    // half-warp, since lane = (ty&1)*16 + tx).
    float as[TN], ad[TN];
    #pragma unroll
    for (int j = 0; j < TN; j++) {
        as[j] = __ldg(att_src + head * Cn + tx * TN + j);
        ad[j] = __ldg(att_dst + head * Cn + tx * TN + j);
    }
    #pragma unroll
    for (int i = 0; i < TM; i++) {
        float ps = 0.f, pd = 0.f;
        #pragma unroll
        for (int j = 0; j < TN; j++) {
            ps = fmaf(acc[i][j], as[j], ps);
            pd = fmaf(acc[i][j], ad[j], pd);
        }
        #pragma unroll
        for (int o = 8; o; o >>= 1) {
            ps += __shfl_xor_sync(0xffffffffu, ps, o, 16);
            pd += __shfl_xor_sync(0xffffffffu, pd, o, 16);
        }
        if (tx == 0) {
            int gRow = rowBlk + ty * TM + i;
            if (gRow < M) {
                g_asrc[gRow * Hh + head] = ps;
                g_adst[gRow * Hh + head] = pd;
            }
        }
    }
}

// ---------------- kernel 2: softmax denominators (no max pass) ---------------
// one thread per edge, all 5 heads
__global__ void denom_kernel(const int* __restrict__ ei, int E, int Etot) {
    int e = blockIdx.x * blockDim.x + threadIdx.x;
    if (e >= Etot) return;
    int src, dst;
    if (e < E) { src = ei[e]; dst = ei[E + e]; }
    else       { src = e - E; dst = src; }
    #pragma unroll
    for (int h = 0; h < Hh; h++) {
        float v = g_asrc[src * Hh + h] + g_adst[dst * Hh + h];
        v = v > 0.f ? v : NEG_SLOPE * v;
        atomicAdd(&g_denom[dst * Hh + h], __expf(v));
    }
}

// ---------------- kernel 3: weighted scatter, warp per edge, vec4 atomics ----
__global__ __launch_bounds__(256)
void scatter_kernel(const int* __restrict__ ei,
                    float* __restrict__ out, int E, int Etot) {
    int e = blockIdx.x * (blockDim.x >> 5) + (threadIdx.x >> 5);
    if (e >= Etot) return;
    int lane = threadIdx.x & 31;

    int src, dst;
    if (e < E) { src = ei[e]; dst = ei[E + e]; }
    else       { src = e - E; dst = src; }

    // lanes 0..4 compute the per-head weight (recompute exp, fold head-mean)
    float wv = 0.f;
    if (lane < Hh) {
        float v = g_asrc[src * Hh + lane] + g_adst[dst * Hh + lane];
        v = v > 0.f ? v : NEG_SLOPE * v;
        wv = __expf(v) / (g_denom[dst * Hh + lane] + EPSV) * (1.0f / Hh);
    }
    float w0 = __shfl_sync(0xffffffffu, wv, 0);
    float w1 = __shfl_sync(0xffffffffu, wv, 1);
    float w2 = __shfl_sync(0xffffffffu, wv, 2);
    float w3 = __shfl_sync(0xffffffffu, wv, 3);
    float w4 = __shfl_sync(0xffffffffu, wv, 4);

    // each lane: 4 channels, accumulate over 5 heads
    const float4* hp = (const float4*)(g_h + (size_t)src * HC) + lane;
    float4 r0 = hp[0 * 32];
    float4 r1 = hp[1 * 32];
    float4 r2 = hp[2 * 32];
    float4 r3 = hp[3 * 32];
    float4 r4 = hp[4 * 32];

    float4 a;
    a.x = w0*r0.x + w1*r1.x + w2*r2.x + w3*r3.x + w4*r4.x;
    a.y = w0*r0.y + w1*r1.y + w2*r2.y + w3*r3.y + w4*r4.y;
    a.z = w0*r0.z + w1*r1.z + w2*r2.z + w3*r3.z + w4*r4.z;
    a.w = w0*r0.w + w1*r1.w + w2*r2.w + w3*r3.w + w4*r4.w;

    float* op = out + (size_t)dst * Cn + lane * 4;
    asm volatile("red.global.add.v4.f32 [%0], {%1, %2, %3, %4};"
                 :: "l"(op), "f"(a.x), "f"(a.y), "f"(a.z), "f"(a.w)
                 : "memory");
}

// ---------------- launch ------------------------------------------------------
extern "C" void kernel_launch(void* const* d_in, const int* in_sizes, int n_in,
                              void* d_out, int out_size) {
    const float* features = (const float*)d_in[0];
    const float* W        = (const float*)d_in[1];
    const float* att_src  = (const float*)d_in[2];
    const float* att_dst  = (const float*)d_in[3];
    const float* bias     = (const float*)d_in[4];
    const int*   ei       = (const int*)d_in[5];   // int32 (jax x64 disabled)
    float*       out      = (float*)d_out;

    const int Nn   = in_sizes[0] / Cn;   // 20000
    const int E    = in_sizes[5] / 2;    // 320000
    const int Etot = E + Nn;             // 340000

    // 0) out = features + bias; zero denom
    {
        int work = Nn * Cn;
        init_kernel<<<(work + 255) / 256, 256>>>(features, bias, out, Nn);
    }

    // 1) h = features @ W with fused attention logits
    {
        dim3 grid(Hh, (Nn + BM - 1) / BM);   // (5, 157)
        sgemm_kernel<<<grid, 256>>>(features, W, att_src, att_dst, Nn);
    }

    // 2) softmax denominators
    denom_kernel<<<(Etot + 255) / 256, 256>>>(ei, E, Etot);

    // 3) weighted scatter (8 edges per 256-thread block)
    scatter_kernel<<<(Etot + 7) / 8, 256>>>(ei, out, E, Etot);
}

// round 5
// speedup vs baseline: 1.8800x; 1.1395x over previous
#include <cuda_runtime.h>
#include <cuda_fp16.h>
#include <math.h>

// Problem constants (fixed by the dataset)
#define Cn   128          // channels
#define Hh   5            // heads
#define HC   (Hh*Cn)      // 640
#define MAXN 20000
#define MAXE 320000
#define MAXET (MAXE + MAXN)
#define EPSV 1e-16f
#define NEG_SLOPE 0.2f

// ---------------- scratch (static device globals; no runtime alloc) ----------
__device__ __half g_h[(size_t)MAXN * HC];      // projected features [N,H,C] fp16 (25.6 MB)
__device__ float  g_asrc[MAXN * Hh];
__device__ float  g_adst[MAXN * Hh];
__device__ float  g_denom[MAXN * Hh];

// ---------------- kernel 0: init out = features + bias; zero denom ----------
__global__ void init_kernel(const float* __restrict__ features,
                            const float* __restrict__ bias,
                            float* __restrict__ out, int Nn) {
    int i = blockIdx.x * blockDim.x + threadIdx.x;
    int NC = Nn * Cn;
    if (i < NC) out[i] = features[i] + bias[i & (Cn - 1)];
    if (i < Nn * Hh) g_denom[i] = 0.0f;
}

// ---------------- kernel 1: SGEMM h = features @ W (fp16 store) + logits -----
#define BM 128
#define BN 128
#define BK 8
#define TM 8
#define TN 8
__global__ __launch_bounds__(256, 2)
void sgemm_kernel(const float* __restrict__ A,
                  const float* __restrict__ B,
                  const float* __restrict__ att_src,
                  const float* __restrict__ att_dst,
                  int M) {
    __shared__ float As[BK][BM];
    __shared__ float Bs[BK][BN];

    const int tid    = threadIdx.x;
    const int rowBlk = blockIdx.y * BM;
    const int head   = blockIdx.x;          // BN == Cn: one head per block col
    const int colBlk = head * BN;

    const int tx = tid & 15;
    const int ty = tid >> 4;

    const int aRow  = tid >> 1;
    const int aCol4 = (tid & 1) << 2;
    const int bRow  = tid >> 5;
    const int bCol4 = (tid & 31) << 2;

    float acc[TM][TN];
    #pragma unroll
    for (int i = 0; i < TM; i++)
        #pragma unroll
        for (int j = 0; j < TN; j++) acc[i][j] = 0.0f;

    for (int k0 = 0; k0 < Cn; k0 += BK) {
        float4 av = make_float4(0.f, 0.f, 0.f, 0.f);
        int gRow = rowBlk + aRow;
        if (gRow < M)
            av = *(const float4*)(A + (size_t)gRow * Cn + k0 + aCol4);
        As[aCol4 + 0][aRow] = av.x;
        As[aCol4 + 1][aRow] = av.y;
        As[aCol4 + 2][aRow] = av.z;
        As[aCol4 + 3][aRow] = av.w;
        float4 bv = *(const float4*)(B + (size_t)(k0 + bRow) * HC + colBlk + bCol4);
        *(float4*)&Bs[bRow][bCol4] = bv;
        __syncthreads();

        #pragma unroll
        for (int k = 0; k < BK; k++) {
            float a[TM], b[TN];
            float4 a0 = *(const float4*)&As[k][ty * TM];
            float4 a1 = *(const float4*)&As[k][ty * TM + 4];
            a[0]=a0.x; a[1]=a0.y; a[2]=a0.z; a[3]=a0.w;
            a[4]=a1.x; a[5]=a1.y; a[6]=a1.z; a[7]=a1.w;
            float4 b0 = *(const float4*)&Bs[k][tx * TN];
            float4 b1 = *(const float4*)&Bs[k][tx * TN + 4];
            b[0]=b0.x; b[1]=b0.y; b[2]=b0.z; b[3]=b0.w;
            b[4]=b1.x; b[5]=b1.y; b[6]=b1.z; b[7]=b1.w;
            #pragma unroll
            for (int i = 0; i < TM; i++)
                #pragma unroll
                for (int j = 0; j < TN; j++)
                    acc[i][j] = fmaf(a[i], b[j], acc[i][j]);
        }
        __syncthreads();
    }

    // store h tile as fp16 (8 halves = one uint4 per row-slice per thread)
    #pragma unroll
    for (int i = 0; i < TM; i++) {
        int gRow = rowBlk + ty * TM + i;
        if (gRow < M) {
            __half2 p0 = __floats2half2_rn(acc[i][0], acc[i][1]);
            __half2 p1 = __floats2half2_rn(acc[i][2], acc[i][3]);
            __half2 p2 = __floats2half2_rn(acc[i][4], acc[i][5]);
            __half2 p3 = __floats2half2_rn(acc[i][6], acc[i][7]);
            uint4 pk;
            pk.x = *(unsigned*)&p0; pk.y = *(unsigned*)&p1;
            pk.z = *(unsigned*)&p2; pk.w = *(unsigned*)&p3;
            *(uint4*)(g_h + (size_t)gRow * HC + colBlk + tx * TN) = pk;
        }
    }

    // fused attention logits (fp32 accumulators), reduce across tx half-warp
    float as[TN], ad[TN];
    #pragma unroll
    for (int j = 0; j < TN; j++) {
        as[j] = __ldg(att_src + head * Cn + tx * TN + j);
        ad[j] = __ldg(att_dst + head * Cn + tx * TN + j);
    }
    #pragma unroll
    for (int i = 0; i < TM; i++) {
        float ps = 0.f, pd = 0.f;
        #pragma unroll
        for (int j = 0; j < TN; j++) {
            ps = fmaf(acc[i][j], as[j], ps);
            pd = fmaf(acc[i][j], ad[j], pd);
        }
        #pragma unroll
        for (int o = 8; o; o >>= 1) {
            ps += __shfl_xor_sync(0xffffffffu, ps, o, 16);
            pd += __shfl_xor_sync(0xffffffffu, pd, o, 16);
        }
        if (tx == 0) {
            int gRow = rowBlk + ty * TM + i;
            if (gRow < M) {
                g_asrc[gRow * Hh + head] = ps;
                g_adst[gRow * Hh + head] = pd;
            }
        }
    }
}

// ---------------- kernel 2: softmax denominators (no max pass) ---------------
__global__ void denom_kernel(const int* __restrict__ ei, int E, int Etot) {
    int e = blockIdx.x * blockDim.x + threadIdx.x;
    if (e >= Etot) return;
    int src, dst;
    if (e < E) { src = ei[e]; dst = ei[E + e]; }
    else       { src = e - E; dst = src; }
    #pragma unroll
    for (int h = 0; h < Hh; h++) {
        float v = g_asrc[src * Hh + h] + g_adst[dst * Hh + h];
        v = v > 0.f ? v : NEG_SLOPE * v;
        atomicAdd(&g_denom[dst * Hh + h], __expf(v));
    }
}

// ---------------- helper: accumulate 4 fp16 channels of one head -------------
__device__ __forceinline__ void acc_head(float4& acc4, uint2 u, float wgt) {
    float2 lo = __half22float2(*(const __half2*)&u.x);
    float2 hi = __half22float2(*(const __half2*)&u.y);
    acc4.x = fmaf(wgt, lo.x, acc4.x);
    acc4.y = fmaf(wgt, lo.y, acc4.y);
    acc4.z = fmaf(wgt, hi.x, acc4.z);
    acc4.w = fmaf(wgt, hi.y, acc4.w);
}

// ---------------- kernel 3: weighted scatter, warp per edge, fp16 h ----------
__global__ __launch_bounds__(256)
void scatter_kernel(const int* __restrict__ ei,
                    float* __restrict__ out, int E, int Etot) {
    int e = blockIdx.x * (blockDim.x >> 5) + (threadIdx.x >> 5);
    if (e >= Etot) return;
    int lane = threadIdx.x & 31;

    int src, dst;
    if (e < E) { src = ei[e]; dst = ei[E + e]; }
    else       { src = e - E; dst = src; }

    // lanes 0..4 compute per-head weight (recompute exp, fold head-mean)
    float wv = 0.f;
    if (lane < Hh) {
        float v = g_asrc[src * Hh + lane] + g_adst[dst * Hh + lane];
        v = v > 0.f ? v : NEG_SLOPE * v;
        wv = __expf(v) / (g_denom[dst * Hh + lane] + EPSV) * (1.0f / Hh);
    }
    float w0 = __shfl_sync(0xffffffffu, wv, 0);
    float w1 = __shfl_sync(0xffffffffu, wv, 1);
    float w2 = __shfl_sync(0xffffffffu, wv, 2);
    float w3 = __shfl_sync(0xffffffffu, wv, 3);
    float w4 = __shfl_sync(0xffffffffu, wv, 4);

    // each lane: 4 channels (one uint2 = 4 halves) per head, accumulate fp32
    const uint2* hp = (const uint2*)(g_h + (size_t)src * HC) + lane; // head row = 32 uint2
    uint2 u0 = hp[0 * 32];
    uint2 u1 = hp[1 * 32];
    uint2 u2 = hp[2 * 32];
    uint2 u3 = hp[3 * 32];
    uint2 u4 = hp[4 * 32];

    float4 a = make_float4(0.f, 0.f, 0.f, 0.f);
    acc_head(a, u0, w0);
    acc_head(a, u1, w1);
    acc_head(a, u2, w2);
    acc_head(a, u3, w3);
    acc_head(a, u4, w4);

    float* op = out + (size_t)dst * Cn + lane * 4;
    asm volatile("red.global.add.v4.f32 [%0], {%1, %2, %3, %4};"
                 :: "l"(op), "f"(a.x), "f"(a.y), "f"(a.z), "f"(a.w)
                 : "memory");
}

// ---------------- launch ------------------------------------------------------
extern "C" void kernel_launch(void* const* d_in, const int* in_sizes, int n_in,
                              void* d_out, int out_size) {
    const float* features = (const float*)d_in[0];
    const float* W        = (const float*)d_in[1];
    const float* att_src  = (const float*)d_in[2];
    const float* att_dst  = (const float*)d_in[3];
    const float* bias     = (const float*)d_in[4];
    const int*   ei       = (const int*)d_in[5];   // int32 (jax x64 disabled)
    float*       out      = (float*)d_out;

    const int Nn   = in_sizes[0] / Cn;   // 20000
    const int E    = in_sizes[5] / 2;    // 320000
    const int Etot = E + Nn;             // 340000

    // 0) out = features + bias; zero denom
    {
        int work = Nn * Cn;
        init_kernel<<<(work + 255) / 256, 256>>>(features, bias, out, Nn);
    }

    // 1) h = features @ W (fp16 store) with fused attention logits
    {
        dim3 grid(Hh, (Nn + BM - 1) / BM);   // (5, 157)
        sgemm_kernel<<<grid, 256>>>(features, W, att_src, att_dst, Nn);
    }

    // 2) softmax denominators
    denom_kernel<<<(Etot + 255) / 256, 256>>>(ei, E, Etot);

    // 3) weighted scatter (8 edges per 256-thread block)
    scatter_kernel<<<(Etot + 7) / 8, 256>>>(ei, out, E, Etot);
}

// round 6
// speedup vs baseline: 2.5402x; 1.3512x over previous
#include <cuda_runtime.h>
#include <cuda_fp16.h>
#include <math.h>

// Problem constants (fixed by the dataset)
#define Cn   128          // channels
#define Hh   5            // heads
#define HC   (Hh*Cn)      // 640
#define MAXN 20000
#define MAXE 320000
#define MAXET (MAXE + MAXN)
#define EPSV 1e-16f
#define NEG_SLOPE 0.2f

// ---------------- scratch (static device globals; no runtime alloc) ----------
__device__ __half g_h[(size_t)MAXN * HC];      // projected features [N,H,C] fp16 (25.6 MB)
__device__ float  g_asrc[MAXN * Hh];
__device__ float  g_adst[MAXN * Hh];
__device__ float  g_denom[MAXN * Hh];

// ---------------- kernel 0: init out = features + bias; zero denom ----------
__global__ void init_kernel(const float* __restrict__ features,
                            const float* __restrict__ bias,
                            float* __restrict__ out, int Nn) {
    int i = blockIdx.x * blockDim.x + threadIdx.x;
    int NC = Nn * Cn;
    if (i < NC) out[i] = features[i] + bias[i & (Cn - 1)];
    if (i < Nn * Hh) g_denom[i] = 0.0f;
}

// ---------------- tf32 tensor-core GEMM + fused logits -----------------------
// h = features[N,128] @ W[128,640], stored fp16 to g_h; per-(row,head)
// attention logits computed from the fp16 tile (consistent with scatter).
#define TBM  128
#define TBK  32     // K chunk
#define APAD 36     // As row stride (floats): bank = (4*gid+tig)%32, conflict-free
#define BPAD 132    // Bs row stride (floats): bank = (4*tig+gid)%32, conflict-free
#define CH2S 69     // Cs row stride in half2 units (odd word stride -> conflict-free rows)

__device__ __forceinline__ float tf32r(float x) {
    unsigned r;
    asm("cvt.rna.tf32.f32 %0, %1;" : "=r"(r) : "f"(x));
    return __uint_as_float(r);
}

__device__ __forceinline__ void mma_tf32(float d[4], const unsigned a[4],
                                         const unsigned b[2]) {
    asm volatile(
        "mma.sync.aligned.m16n8k8.row.col.f32.tf32.tf32.f32 "
        "{%0,%1,%2,%3}, {%4,%5,%6,%7}, {%8,%9}, {%0,%1,%2,%3};"
        : "+f"(d[0]), "+f"(d[1]), "+f"(d[2]), "+f"(d[3])
        : "r"(a[0]), "r"(a[1]), "r"(a[2]), "r"(a[3]), "r"(b[0]), "r"(b[1]));
}

__global__ __launch_bounds__(256, 2)
void gemm_tc_kernel(const float* __restrict__ A,
                    const float* __restrict__ B,
                    const float* __restrict__ att_src,
                    const float* __restrict__ att_dst,
                    int M) {
    // union: mainloop As(18432B)+Bs(16896B) == epilogue Cs(128*69*4 = 35328B)
    __shared__ __align__(16) char smem_raw[35328];
    float*    As = (float*)smem_raw;               // [128][36]
    float*    Bs = (float*)(smem_raw + 18432);     // [32][132]
    unsigned* Cs = (unsigned*)smem_raw;            // [128][69] half2 pairs

    const int tid    = threadIdx.x;
    const int head   = blockIdx.x;
    const int rowBlk = blockIdx.y * TBM;
    const int lane   = tid & 31;
    const int wid    = tid >> 5;
    const int warpM  = wid & 1;          // 0..1 -> 64 rows each
    const int warpN  = wid >> 1;         // 0..3 -> 32 cols each
    const int gid    = lane >> 2;        // 0..7
    const int tig    = lane & 3;         // 0..3

    float acc[4][4][4];                  // [mtile][ntile][reg]
    #pragma unroll
    for (int m = 0; m < 4; m++)
        #pragma unroll
        for (int n = 0; n < 4; n++)
            #pragma unroll
            for (int r = 0; r < 4; r++) acc[m][n][r] = 0.0f;

    // global->smem load mappings
    const int aRow   = tid >> 1;             // 0..127
    const int aCbase = (tid & 1) * 16;       // float col base (loads 4 float4)
    const int bKrow  = tid >> 3;             // 0..31
    const int bF4    = tid & 7;              // f4 col base (loads 4 float4)
    const int gARow  = rowBlk + aRow;

    for (int kc = 0; kc < Cn; kc += TBK) {
        // A chunk [128][32] (tf32-rounded)
        #pragma unroll
        for (int j = 0; j < 4; j++) {
            float4 v = make_float4(0.f, 0.f, 0.f, 0.f);
            if (gARow < M)
                v = *(const float4*)(A + (size_t)gARow * Cn + kc + aCbase + 4 * j);
            v.x = tf32r(v.x); v.y = tf32r(v.y); v.z = tf32r(v.z); v.w = tf32r(v.w);
            *(float4*)(As + aRow * APAD + aCbase + 4 * j) = v;
        }
        // B chunk [32][128] (tf32-rounded)
        #pragma unroll
        for (int j = 0; j < 4; j++) {
            int col = (bF4 + 8 * j) * 4;
            float4 v = *(const float4*)(B + (size_t)(kc + bKrow) * HC + head * Cn + col);
            v.x = tf32r(v.x); v.y = tf32r(v.y); v.z = tf32r(v.z); v.w = tf32r(v.w);
            *(float4*)(Bs + bKrow * BPAD + col) = v;
        }
        __syncthreads();

        #pragma unroll
        for (int kk = 0; kk < 4; kk++) {
            const int kb = kk * 8;
            unsigned a[4][4], b[4][2];
            #pragma unroll
            for (int m = 0; m < 4; m++) {
                int r0 = warpM * 64 + m * 16 + gid;
                a[m][0] = __float_as_uint(As[r0 * APAD + kb + tig]);
                a[m][1] = __float_as_uint(As[(r0 + 8) * APAD + kb + tig]);
                a[m][2] = __float_as_uint(As[r0 * APAD + kb + tig + 4]);
                a[m][3] = __float_as_uint(As[(r0 + 8) * APAD + kb + tig + 4]);
            }
            #pragma unroll
            for (int n = 0; n < 4; n++) {
                int cb = warpN * 32 + n * 8 + gid;
                b[n][0] = __float_as_uint(Bs[(kb + tig) * BPAD + cb]);
                b[n][1] = __float_as_uint(Bs[(kb + tig + 4) * BPAD + cb]);
            }
            #pragma unroll
            for (int m = 0; m < 4; m++)
                #pragma unroll
                for (int n = 0; n < 4; n++)
                    mma_tf32(acc[m][n], a[m], b[n]);
        }
        __syncthreads();
    }

    // epilogue: stage tile as half2 into Cs (aliases As/Bs; all mma reads done)
    #pragma unroll
    for (int m = 0; m < 4; m++) {
        int r0 = warpM * 64 + m * 16 + gid;
        #pragma unroll
        for (int n = 0; n < 4; n++) {
            int ch = warpN * 16 + n * 4 + tig;     // half2 column index
            __half2 h01 = __floats2half2_rn(acc[m][n][0], acc[m][n][1]);
            __half2 h23 = __floats2half2_rn(acc[m][n][2], acc[m][n][3]);
            Cs[r0 * CH2S + ch]       = *(unsigned*)&h01;
            Cs[(r0 + 8) * CH2S + ch] = *(unsigned*)&h23;
        }
    }
    __syncthreads();

    // logits per row (threads 0..127), from the fp16 values the scatter will use
    if (tid < TBM) {
        int gRow = rowBlk + tid;
        if (gRow < M) {
            const float* asv = att_src + head * Cn;
            const float* adv = att_dst + head * Cn;
            float ps = 0.f, pd = 0.f;
            #pragma unroll 8
            for (int i = 0; i < 64; i++) {
                unsigned u = Cs[tid * CH2S + i];
                float2 f = __half22float2(*(__half2*)&u);
                ps = fmaf(f.x, __ldg(asv + 2 * i), ps);
                ps = fmaf(f.y, __ldg(asv + 2 * i + 1), ps);
                pd = fmaf(f.x, __ldg(adv + 2 * i), pd);
                pd = fmaf(f.y, __ldg(adv + 2 * i + 1), pd);
            }
            g_asrc[gRow * Hh + head] = ps;
            g_adst[gRow * Hh + head] = pd;
        }
    }

    // coalesced fp16 store to g_h
    unsigned* gh = (unsigned*)g_h;
    #pragma unroll
    for (int i = 0; i < 32; i++) {
        int idx  = i * 256 + tid;
        int row  = idx >> 6;
        int ch   = idx & 63;
        int gRow = rowBlk + row;
        if (gRow < M)
            gh[(size_t)gRow * (HC / 2) + head * 64 + ch] = Cs[row * CH2S + ch];
    }
}

// ---------------- kernel 2: softmax denominators (no max pass) ---------------
__global__ void denom_kernel(const int* __restrict__ ei, int E, int Etot) {
    int e = blockIdx.x * blockDim.x + threadIdx.x;
    if (e >= Etot) return;
    int src, dst;
    if (e < E) { src = ei[e]; dst = ei[E + e]; }
    else       { src = e - E; dst = src; }
    #pragma unroll
    for (int h = 0; h < Hh; h++) {
        float v = g_asrc[src * Hh + h] + g_adst[dst * Hh + h];
        v = v > 0.f ? v : NEG_SLOPE * v;
        atomicAdd(&g_denom[dst * Hh + h], __expf(v));
    }
}

// ---------------- helper: accumulate 4 fp16 channels of one head -------------
__device__ __forceinline__ void acc_head(float4& acc4, uint2 u, float wgt) {
    float2 lo = __half22float2(*(const __half2*)&u.x);
    float2 hi = __half22float2(*(const __half2*)&u.y);
    acc4.x = fmaf(wgt, lo.x, acc4.x);
    acc4.y = fmaf(wgt, lo.y, acc4.y);
    acc4.z = fmaf(wgt, hi.x, acc4.z);
    acc4.w = fmaf(wgt, hi.y, acc4.w);
}

// ---------------- kernel 3: weighted scatter, warp per edge, fp16 h ----------
__global__ __launch_bounds__(256)
void scatter_kernel(const int* __restrict__ ei,
                    float* __restrict__ out, int E, int Etot) {
    int e = blockIdx.x * (blockDim.x >> 5) + (threadIdx.x >> 5);
    if (e >= Etot) return;
    int lane = threadIdx.x & 31;

    int src, dst;
    if (e < E) { src = ei[e]; dst = ei[E + e]; }
    else       { src = e - E; dst = src; }

    float wv = 0.f;
    if (lane < Hh) {
        float v = g_asrc[src * Hh + lane] + g_adst[dst * Hh + lane];
        v = v > 0.f ? v : NEG_SLOPE * v;
        wv = __expf(v) / (g_denom[dst * Hh + lane] + EPSV) * (1.0f / Hh);
    }
    float w0 = __shfl_sync(0xffffffffu, wv, 0);
    float w1 = __shfl_sync(0xffffffffu, wv, 1);
    float w2 = __shfl_sync(0xffffffffu, wv, 2);
    float w3 = __shfl_sync(0xffffffffu, wv, 3);
    float w4 = __shfl_sync(0xffffffffu, wv, 4);

    const uint2* hp = (const uint2*)(g_h + (size_t)src * HC) + lane;
    uint2 u0 = hp[0 * 32];
    uint2 u1 = hp[1 * 32];
    uint2 u2 = hp[2 * 32];
    uint2 u3 = hp[3 * 32];
    uint2 u4 = hp[4 * 32];

    float4 a = make_float4(0.f, 0.f, 0.f, 0.f);
    acc_head(a, u0, w0);
    acc_head(a, u1, w1);
    acc_head(a, u2, w2);
    acc_head(a, u3, w3);
    acc_head(a, u4, w4);

    float* op = out + (size_t)dst * Cn + lane * 4;
    asm volatile("red.global.add.v4.f32 [%0], {%1, %2, %3, %4};"
                 :: "l"(op), "f"(a.x), "f"(a.y), "f"(a.z), "f"(a.w)
                 : "memory");
}

// ---------------- launch ------------------------------------------------------
extern "C" void kernel_launch(void* const* d_in, const int* in_sizes, int n_in,
                              void* d_out, int out_size) {
    const float* features = (const float*)d_in[0];
    const float* W        = (const float*)d_in[1];
    const float* att_src  = (const float*)d_in[2];
    const float* att_dst  = (const float*)d_in[3];
    const float* bias     = (const float*)d_in[4];
    const int*   ei       = (const int*)d_in[5];   // int32 (jax x64 disabled)
    float*       out      = (float*)d_out;

    const int Nn   = in_sizes[0] / Cn;   // 20000
    const int E    = in_sizes[5] / 2;    // 320000
    const int Etot = E + Nn;             // 340000

    // 0) out = features + bias; zero denom
    {
        int work = Nn * Cn;
        init_kernel<<<(work + 255) / 256, 256>>>(features, bias, out, Nn);
    }

    // 1) h = features @ W via tf32 tensor cores, fused logits + fp16 store
    {
        dim3 grid(Hh, (Nn + TBM - 1) / TBM);   // (5, 157)
        gemm_tc_kernel<<<grid, 256>>>(features, W, att_src, att_dst, Nn);
    }

    // 2) softmax denominators
    denom_kernel<<<(Etot + 255) / 256, 256>>>(ei, E, Etot);

    // 3) weighted scatter (8 edges per 256-thread block)
    scatter_kernel<<<(Etot + 7) / 8, 256>>>(ei, out, E, Etot);
}